// round 1
// baseline (speedup 1.0000x reference)
#include <cuda_runtime.h>
#include <math.h>

// Problem constants
#define NB    4
#define NC    17
#define NH    128
#define NW    128
#define NPC   51      // 3*C
#define NWID  128     // hidden width
#define NSTEP 48
#define ALIVE_IDX 3
#define ALIVE_THR 0.1f
#define UPDATE_P  0.5f

#define CHW   (NC*NH*NW)          // 278528
#define BCHW  (NB*CHW)            // 1114112
#define FINAL_ELEMS (NB*4*NH*NW)  // 262144

// Static scratch for the un-alive-masked "new" state (no allocation allowed).
__device__ float g_newpre[BCHW];

__device__ __forceinline__ float ldz(const float* __restrict__ ch, int y, int x) {
    if (y < 0 || y >= NH || x < 0 || x >= NW) return 0.0f;
    return __ldg(ch + y * NW + x);
}

// ---------------------------------------------------------------------------
// Kernel A: per-pixel sobel + rotation + MLP + stochastic update.
// Writes un-masked new state to g_newpre.
// ---------------------------------------------------------------------------
__global__ __launch_bounds__(256, 2)
void nca_step_kernel(const float* __restrict__ state,   // old state [B,C,H,W]
                     const float* __restrict__ rnd_all, // [STEPS,B,1,H,W]
                     const float* __restrict__ W1,      // [128,51]
                     const float* __restrict__ b1,      // [128]
                     const float* __restrict__ W2,      // [17,128]
                     const float* __restrict__ b2,      // [17]
                     int t)
{
    __shared__ float sW1[NWID * 52];   // rows padded 51 -> 52 (float4 friendly)
    __shared__ float sW2T[NWID * NC];  // transposed: [o][j]
    __shared__ float sB1[NWID];
    __shared__ float sB2[NC];

    const int tid = threadIdx.y * 16 + threadIdx.x;

    for (int i = tid; i < NWID * 52; i += 256) {
        int o = i / 52, c = i - o * 52;
        sW1[i] = (c < NPC) ? W1[o * NPC + c] : 0.0f;
    }
    for (int i = tid; i < NWID * NC; i += 256) {
        int o = i / NC, j = i - o * NC;
        sW2T[i] = W2[j * NWID + o];
    }
    if (tid < NWID) sB1[tid] = b1[tid];
    if (tid < NC)   sB2[tid] = b2[tid];
    __syncthreads();

    const int x = blockIdx.x * 16 + threadIdx.x;
    const int y = blockIdx.y * 16 + threadIdx.y;
    const int b = blockIdx.z;

    // p[0..16] = state, p[17..33] = gx (later px), p[34..50] = gy (later py)
    float p[52];
    p[51] = 0.0f;

    #pragma unroll
    for (int c = 0; c < NC; c++) {
        const float* ch = state + (b * NC + c) * (NH * NW);
        float a00 = ldz(ch, y - 1, x - 1);
        float a01 = ldz(ch, y - 1, x    );
        float a02 = ldz(ch, y - 1, x + 1);
        float a10 = ldz(ch, y,     x - 1);
        float a11 = __ldg(ch + y * NW + x);
        float a12 = ldz(ch, y,     x + 1);
        float a20 = ldz(ch, y + 1, x - 1);
        float a21 = ldz(ch, y + 1, x    );
        float a22 = ldz(ch, y + 1, x + 1);
        p[c] = a11;
        // cross-correlation with SOBEL_X / SOBEL_Y (= SOBEL_X^T), /8
        float gx = ((a02 - a00) + 2.0f * (a12 - a10) + (a22 - a20)) * 0.125f;
        float gy = ((a20 - a00) + 2.0f * (a21 - a01) + (a22 - a02)) * 0.125f;
        p[17 + c] = gx;
        p[34 + c] = gy;
    }

    const float ang = p[16];          // last channel of OLD state
    float sa, ca;
    sincosf(ang, &sa, &ca);

    #pragma unroll
    for (int c = 0; c < NC; c++) {
        float gx = p[17 + c], gy = p[34 + c];
        p[17 + c] = ca * gx + sa * gy;      // px
        p[34 + c] = ca * gy - sa * gx;      // py
    }

    float dx[NC];
    #pragma unroll
    for (int j = 0; j < NC; j++) dx[j] = sB2[j];

    #pragma unroll 4
    for (int o = 0; o < NWID; o++) {
        float acc0 = sB1[o];
        float acc1 = 0.0f;
        const float4* wr = (const float4*)(sW1 + o * 52);
        #pragma unroll
        for (int q = 0; q < 13; q++) {
            float4 w = wr[q];
            acc0 += w.x * p[4 * q + 0] + w.z * p[4 * q + 2];
            acc1 += w.y * p[4 * q + 1] + w.w * p[4 * q + 3];
        }
        float h = fmaxf(acc0 + acc1, 0.0f);
        const float* w2 = sW2T + o * NC;
        #pragma unroll
        for (int j = 0; j < NC; j++) dx[j] += w2[j] * h;
    }

    const float r = __ldg(rnd_all + (((size_t)t * NB + b) * NH + y) * NW + x);
    const float m = (r < UPDATE_P) ? 1.0f : 0.0f;

    const int pix = y * NW + x;
    #pragma unroll
    for (int c = 0; c < NC; c++) {
        g_newpre[(b * NC + c) * (NH * NW) + pix] = p[c] + dx[c] * m;
    }
}

// ---------------------------------------------------------------------------
// Kernel B: alive masking.  pre = maxpool3(old alive) > thr,
// post = maxpool3(newpre alive) > thr, out = newpre * (pre && post).
// Writes dev_path[t]; for the last step also writes final[:, :4].
// ---------------------------------------------------------------------------
__global__ __launch_bounds__(256)
void nca_mask_kernel(const float* __restrict__ oldstate, // [B,C,H,W]
                     float* __restrict__ dev_out,        // dev_path slice [B,C,H,W]
                     float* __restrict__ final_out)      // null unless t==47
{
    const int x = blockIdx.x * 16 + threadIdx.x;
    const int y = blockIdx.y * 16 + threadIdx.y;
    const int b = blockIdx.z;

    const float* oa = oldstate  + (b * NC + ALIVE_IDX) * (NH * NW);
    const float* na = g_newpre  + (b * NC + ALIVE_IDX) * (NH * NW);

    float mo = -1e30f, mn = -1e30f;
    #pragma unroll
    for (int dy = -1; dy <= 1; dy++) {
        int yy = y + dy;
        if (yy < 0 || yy >= NH) continue;
        #pragma unroll
        for (int dxx = -1; dxx <= 1; dxx++) {
            int xx = x + dxx;
            if (xx < 0 || xx >= NW) continue;
            int idx = yy * NW + xx;
            mo = fmaxf(mo, __ldg(oa + idx));
            mn = fmaxf(mn, __ldg(na + idx));
        }
    }
    const float alive = (mo > ALIVE_THR && mn > ALIVE_THR) ? 1.0f : 0.0f;

    const int pix = y * NW + x;
    #pragma unroll
    for (int c = 0; c < NC; c++) {
        float v = g_newpre[(b * NC + c) * (NH * NW) + pix] * alive;
        dev_out[(b * NC + c) * (NH * NW) + pix] = v;
        if (final_out != nullptr && c < 4) {
            final_out[(b * 4 + c) * (NH * NW) + pix] = v;
        }
    }
}

// ---------------------------------------------------------------------------
// Host launcher.  Inputs (metadata order):
//   0 init_state f32 [4,17,128,128]
//   1 rand       f32 [48,4,1,128,128]
//   2 W1         f32 [128,51]
//   3 b1         f32 [128]
//   4 W2         f32 [17,128]
//   5 b2         f32 [17]
// Output f32: final[:, :4] (262144) followed by dev_path (48*4*17*128*128).
// dev_path slices double as the state buffer chain (no extra state storage).
// ---------------------------------------------------------------------------
extern "C" void kernel_launch(void* const* d_in, const int* in_sizes, int n_in,
                              void* d_out, int out_size)
{
    const float* init_state = (const float*)d_in[0];
    const float* rnd        = (const float*)d_in[1];
    const float* W1         = (const float*)d_in[2];
    const float* b1         = (const float*)d_in[3];
    const float* W2         = (const float*)d_in[4];
    const float* b2         = (const float*)d_in[5];

    float* out      = (float*)d_out;
    float* final_p  = out;                 // [4,4,128,128]
    float* dev_path = out + FINAL_ELEMS;   // [48,4,17,128,128]

    dim3 blk(16, 16, 1);
    dim3 grd(NW / 16, NH / 16, NB);

    const float* cur = init_state;
    for (int t = 0; t < NSTEP; t++) {
        nca_step_kernel<<<grd, blk>>>(cur, rnd, W1, b1, W2, b2, t);
        float* dst = dev_path + (size_t)t * BCHW;
        nca_mask_kernel<<<grd, blk>>>(cur, dst, (t == NSTEP - 1) ? final_p : nullptr);
        cur = dst;
    }
}

// round 2
// speedup vs baseline: 1.6636x; 1.6636x over previous
#include <cuda_runtime.h>
#include <math.h>

// Problem constants
#define NB    4
#define NC    17
#define NH    128
#define NW    128
#define HWSZ  (NH*NW)
#define NPC   51
#define NWID  128
#define NSTEP 48
#define ALIVE_IDX 3
#define ALIVE_THR 0.1f

#define CHW   (NC*HWSZ)
#define BCHW  (NB*CHW)
#define FINAL_ELEMS (NB*4*HWSZ)

typedef unsigned long long ull;

// f32x2 packed-pair helpers (Blackwell FFMA2 path)
#define F2FMA(d, a, b, c) asm("fma.rn.f32x2 %0, %1, %2, %3;" : "=l"(d) : "l"(a), "l"(b), "l"(c))
#define F2MUL(d, a, b)    asm("mul.rn.f32x2 %0, %1, %2;"     : "=l"(d) : "l"(a), "l"(b))
#define F2ADD(d, a, b)    asm("add.rn.f32x2 %0, %1, %2;"     : "=l"(d) : "l"(a), "l"(b))
#define PK2(d, lo, hi)    asm("mov.b64 %0, {%1, %2};" : "=l"(d) : "f"(lo), "f"(hi))
#define UPK2(lo, hi, s)   asm("mov.b64 {%0, %1}, %2;" : "=f"(lo), "=f"(hi) : "l"(s))

// Unmasked new alive-channel scratch (race-free input for post-alive maxpool).
__device__ float g_alive[NB * HWSZ];

__device__ __forceinline__ float ldz(const float* __restrict__ ch, int y, int x) {
    if (y < 0 || y >= NH || x < 0 || x >= NW) return 0.0f;
    return __ldg(ch + y * NW + x);
}

// Dynamic smem layout (ull units):
//   sW1d [128*52]  : W1[o][c] duplicated (w,w), rows padded 51->52
//   sW2d [128*18]  : W2^T[o][j] duplicated, rows padded 17->18 (pad = 0)
//   sB1d [128]     : b1 duplicated
//   sB2d [18]      : b2 duplicated (pad 0)
#define S_W1  0
#define S_W2  (128*52)
#define S_B1  (S_W2 + 128*18)
#define S_B2  (S_B1 + 128)
#define SMEM_ULLS (S_B2 + 18)
#define SMEM_BYTES (SMEM_ULLS * 8)

// ---------------------------------------------------------------------------
// Step kernel: 2 pixels per thread via f32x2. Writes unmasked new state
// directly to dev_out and the new alive channel to g_alive.
// ---------------------------------------------------------------------------
__global__ __launch_bounds__(128, 2)
void nca_step_kernel(const float* __restrict__ state,   // [B,C,H,W] (masked prev)
                     const float* __restrict__ rnd_all, // [STEPS,B,1,H,W]
                     const float* __restrict__ W1, const float* __restrict__ b1,
                     const float* __restrict__ W2, const float* __restrict__ b2,
                     float* __restrict__ dev_out,       // [B,C,H,W] (unmasked)
                     int t)
{
    extern __shared__ ull smem[];
    const int tid = threadIdx.x;

    // ---- load duplicated weights ----
    for (int i = tid; i < 128 * 52; i += 128) {
        int o = i / 52, c = i - o * 52;
        float w = (c < NPC) ? W1[o * NPC + c] : 0.0f;
        ull d; PK2(d, w, w); smem[S_W1 + i] = d;
    }
    for (int i = tid; i < 128 * 18; i += 128) {
        int o = i / 18, j = i - o * 18;
        float w = (j < NC) ? W2[j * NWID + o] : 0.0f;
        ull d; PK2(d, w, w); smem[S_W2 + i] = d;
    }
    {
        float w = b1[tid];
        ull d; PK2(d, w, w); smem[S_B1 + tid] = d;
    }
    if (tid < 18) {
        float w = (tid < NC) ? b2[tid] : 0.0f;
        ull d; PK2(d, w, w); smem[S_B2 + tid] = d;
    }

    // bias condition for the empty-space shortcut: relu(b1)=0 and b2=0
    int bias_ok = (b1[tid] <= 0.0f);
    if (tid < NC) bias_ok = bias_ok && (b2[tid] == 0.0f);
    const int allz = __syncthreads_and(bias_ok);   // barrier + reduction

    // ---- pixel pair coordinates ----
    const int pr = tid & 7;            // pair index within 16-wide tile
    const int ly = tid >> 3;           // 0..15
    const int x0 = blockIdx.x * 16 + pr * 2;
    const int y  = blockIdx.y * 16 + ly;
    const int b  = blockIdx.z;

    // ---- conv: 3x4 patch per channel ----
    ull p2[52];
    unsigned nz = 0u;
    const bool interior = (x0 >= 1) && (x0 + 2 < NW) && (y >= 1) && (y + 1 < NH);

    #pragma unroll
    for (int c = 0; c < NC; c++) {
        const float* ch = state + (b * NC + c) * HWSZ + y * NW + x0;
        float r0[4], r1[4], r2[4];
        if (interior) {
            r0[0]=__ldg(ch-NW-1); r0[1]=__ldg(ch-NW); r0[2]=__ldg(ch-NW+1); r0[3]=__ldg(ch-NW+2);
            r1[0]=__ldg(ch-1);    r1[1]=__ldg(ch);    r1[2]=__ldg(ch+1);    r1[3]=__ldg(ch+2);
            r2[0]=__ldg(ch+NW-1); r2[1]=__ldg(ch+NW); r2[2]=__ldg(ch+NW+1); r2[3]=__ldg(ch+NW+2);
        } else {
            const float* chb = state + (b * NC + c) * HWSZ;
            r0[0]=ldz(chb,y-1,x0-1); r0[1]=ldz(chb,y-1,x0); r0[2]=ldz(chb,y-1,x0+1); r0[3]=ldz(chb,y-1,x0+2);
            r1[0]=ldz(chb,y  ,x0-1); r1[1]=ldz(chb,y  ,x0); r1[2]=ldz(chb,y  ,x0+1); r1[3]=ldz(chb,y  ,x0+2);
            r2[0]=ldz(chb,y+1,x0-1); r2[1]=ldz(chb,y+1,x0); r2[2]=ldz(chb,y+1,x0+1); r2[3]=ldz(chb,y+1,x0+2);
        }
        nz |= __float_as_uint(r0[0]) | __float_as_uint(r0[1]) | __float_as_uint(r0[2]) | __float_as_uint(r0[3]);
        nz |= __float_as_uint(r1[0]) | __float_as_uint(r1[1]) | __float_as_uint(r1[2]) | __float_as_uint(r1[3]);
        nz |= __float_as_uint(r2[0]) | __float_as_uint(r2[1]) | __float_as_uint(r2[2]) | __float_as_uint(r2[3]);

        float gxA = ((r0[2]-r0[0]) + 2.0f*(r1[2]-r1[0]) + (r2[2]-r2[0])) * 0.125f;
        float gxB = ((r0[3]-r0[1]) + 2.0f*(r1[3]-r1[1]) + (r2[3]-r2[1])) * 0.125f;
        float gyA = ((r2[0]-r0[0]) + 2.0f*(r2[1]-r0[1]) + (r2[2]-r0[2])) * 0.125f;
        float gyB = ((r2[1]-r0[1]) + 2.0f*(r2[2]-r0[2]) + (r2[3]-r0[3])) * 0.125f;

        ull d;
        PK2(d, r1[1], r1[2]); p2[c]      = d;
        PK2(d, gxA,   gxB  ); p2[17 + c] = d;
        PK2(d, gyA,   gyB  ); p2[34 + c] = d;
    }
    p2[51] = 0ULL;

    float* dout = dev_out + b * CHW + y * NW + x0;
    float* gal  = g_alive + b * HWSZ + y * NW + x0;

    // ---- empty-space shortcut (exact: zero patch + relu(b1)=0 + b2=0 => new=0)
    const bool empty = allz && (nz == 0u);
    if (__all_sync(0xFFFFFFFFu, empty)) {
        #pragma unroll
        for (int c = 0; c < NC; c++)
            *reinterpret_cast<ull*>(dout + c * HWSZ) = 0ULL;
        *reinterpret_cast<ull*>(gal) = 0ULL;
        return;
    }

    // ---- rotation by per-pixel angle (old channel 16) ----
    {
        float angA, angB; UPK2(angA, angB, p2[16]);
        float saA, caA, saB, caB;
        sincosf(angA, &saA, &caA);
        sincosf(angB, &saB, &caB);
        ull ca2, sa2, nsa2;
        PK2(ca2, caA, caB); PK2(sa2, saA, saB); PK2(nsa2, -saA, -saB);
        #pragma unroll
        for (int c = 0; c < NC; c++) {
            ull gx2 = p2[17 + c], gy2 = p2[34 + c], u;
            F2MUL(u, ca2, gx2); F2FMA(u, sa2, gy2, u);  p2[17 + c] = u;  // px
            F2MUL(u, ca2, gy2); F2FMA(u, nsa2, gx2, u); p2[34 + c] = u;  // py
        }
    }

    // ---- MLP: h = relu(W1 p + b1); dx = W2 h + b2 ----
    ull dx2[18];
    #pragma unroll
    for (int j = 0; j < 18; j++) dx2[j] = smem[S_B2 + j];

    const ull* w1r = smem + S_W1;
    const ull* w2r = smem + S_W2;
    const ull* b1r = smem + S_B1;

    #pragma unroll 2
    for (int o = 0; o < NWID; o++) {
        ull acc0 = b1r[o];
        ull acc1 = 0ULL;
        const ulonglong2* r = reinterpret_cast<const ulonglong2*>(w1r);
        #pragma unroll
        for (int q = 0; q < 26; q++) {
            ulonglong2 w = r[q];
            F2FMA(acc0, w.x, p2[2*q],     acc0);
            F2FMA(acc1, w.y, p2[2*q + 1], acc1);
        }
        ull hs; F2ADD(hs, acc0, acc1);
        float hA, hB; UPK2(hA, hB, hs);
        hA = fmaxf(hA, 0.0f); hB = fmaxf(hB, 0.0f);
        ull h2; PK2(h2, hA, hB);

        const ulonglong2* r2 = reinterpret_cast<const ulonglong2*>(w2r);
        #pragma unroll
        for (int q = 0; q < 9; q++) {
            ulonglong2 w = r2[q];
            F2FMA(dx2[2*q],     w.x, h2, dx2[2*q]);
            F2FMA(dx2[2*q + 1], w.y, h2, dx2[2*q + 1]);
        }
        w1r += 52; w2r += 18;
    }

    // ---- stochastic update, unmasked write ----
    const float2 rr = *reinterpret_cast<const float2*>(
        rnd_all + ((size_t)t * NB + b) * HWSZ + y * NW + x0);
    float mA = (rr.x < 0.5f) ? 1.0f : 0.0f;
    float mB = (rr.y < 0.5f) ? 1.0f : 0.0f;
    ull m2; PK2(m2, mA, mB);

    #pragma unroll
    for (int c = 0; c < NC; c++) {
        ull nv; F2FMA(nv, dx2[c], m2, p2[c]);   // new = state + dx*mask
        *reinterpret_cast<ull*>(dout + c * HWSZ) = nv;
        if (c == ALIVE_IDX) *reinterpret_cast<ull*>(gal) = nv;
    }
}

// ---------------------------------------------------------------------------
// Mask kernel: zero out dead pixels in-place (alive pixels already correct).
// pre = maxpool3(old alive) > thr ; post = maxpool3(g_alive) > thr.
// ---------------------------------------------------------------------------
__global__ __launch_bounds__(256)
void nca_mask_kernel(const float* __restrict__ oldstate,
                     float* __restrict__ dev,           // dev_path[t], in-place
                     float* __restrict__ final_out)     // null unless last step
{
    const int x = blockIdx.x * 16 + threadIdx.x;
    const int y = blockIdx.y * 16 + threadIdx.y;
    const int b = blockIdx.z;

    const float* oa = oldstate + (b * NC + ALIVE_IDX) * HWSZ;
    const float* na = g_alive + b * HWSZ;

    float mo = -1e30f, mn = -1e30f;
    #pragma unroll
    for (int dy = -1; dy <= 1; dy++) {
        int yy = y + dy;
        if (yy < 0 || yy >= NH) continue;
        #pragma unroll
        for (int dxx = -1; dxx <= 1; dxx++) {
            int xx = x + dxx;
            if (xx < 0 || xx >= NW) continue;
            int idx = yy * NW + xx;
            mo = fmaxf(mo, __ldg(oa + idx));
            mn = fmaxf(mn, __ldg(na + idx));
        }
    }
    const bool alive = (mo > ALIVE_THR) && (mn > ALIVE_THR);
    const int pix = y * NW + x;

    if (!alive) {
        #pragma unroll
        for (int c = 0; c < NC; c++)
            dev[(b * NC + c) * HWSZ + pix] = 0.0f;
    }
    if (final_out != nullptr) {
        #pragma unroll
        for (int c = 0; c < 4; c++)
            final_out[(b * 4 + c) * HWSZ + pix] =
                alive ? __ldg(dev + (b * NC + c) * HWSZ + pix) : 0.0f;
    }
}

// ---------------------------------------------------------------------------
// Inputs: 0 init_state [4,17,128,128], 1 rand [48,4,1,128,128],
//         2 W1 [128,51], 3 b1 [128], 4 W2 [17,128], 5 b2 [17]
// Output f32: final[:, :4] (262144) then dev_path (48*4*17*128*128).
// dev_path slices double as the state chain.
// ---------------------------------------------------------------------------
extern "C" void kernel_launch(void* const* d_in, const int* in_sizes, int n_in,
                              void* d_out, int out_size)
{
    const float* init_state = (const float*)d_in[0];
    const float* rnd        = (const float*)d_in[1];
    const float* W1         = (const float*)d_in[2];
    const float* b1         = (const float*)d_in[3];
    const float* W2         = (const float*)d_in[4];
    const float* b2         = (const float*)d_in[5];

    float* out      = (float*)d_out;
    float* final_p  = out;
    float* dev_path = out + FINAL_ELEMS;

    cudaFuncSetAttribute(nca_step_kernel,
                         cudaFuncAttributeMaxDynamicSharedMemorySize, SMEM_BYTES);

    dim3 sblk(128, 1, 1);
    dim3 sgrd(NW / 16, NH / 16, NB);
    dim3 mblk(16, 16, 1);
    dim3 mgrd(NW / 16, NH / 16, NB);

    const float* cur = init_state;
    for (int t = 0; t < NSTEP; t++) {
        float* dst = dev_path + (size_t)t * BCHW;
        nca_step_kernel<<<sgrd, sblk, SMEM_BYTES>>>(cur, rnd, W1, b1, W2, b2, dst, t);
        nca_mask_kernel<<<mgrd, mblk>>>(cur, dst, (t == NSTEP - 1) ? final_p : nullptr);
        cur = dst;
    }
}

// round 3
// speedup vs baseline: 2.0354x; 1.2235x over previous
#include <cuda_runtime.h>
#include <math.h>

// Problem constants
#define NB    4
#define NC    17
#define NH    128
#define NW    128
#define HWSZ  (NH*NW)
#define NPC   51
#define NWID  128
#define NSTEP 48
#define ALIVE_IDX 3
#define ALIVE_THR 0.1f

#define CHW   (NC*HWSZ)
#define BCHW  (NB*CHW)
#define FINAL_ELEMS (NB*4*HWSZ)
#define NBLK  256

typedef unsigned long long ull;

// f32x2 packed-pair helpers (Blackwell FFMA2 path)
#define F2FMA(d, a, b, c) asm("fma.rn.f32x2 %0, %1, %2, %3;" : "=l"(d) : "l"(a), "l"(b), "l"(c))
#define F2MUL(d, a, b)    asm("mul.rn.f32x2 %0, %1, %2;"     : "=l"(d) : "l"(a), "l"(b), "l"(c))
#define F2MUL2(d, a, b)   asm("mul.rn.f32x2 %0, %1, %2;"     : "=l"(d) : "l"(a), "l"(b))
#define F2ADD(d, a, b)    asm("add.rn.f32x2 %0, %1, %2;"     : "=l"(d) : "l"(a), "l"(b))
#define PK2(d, lo, hi)    asm("mov.b64 %0, {%1, %2};" : "=l"(d) : "f"(lo), "f"(hi))
#define UPK2(lo, hi, s)   asm("mov.b64 {%0, %1}, %2;" : "=f"(lo), "=f"(hi) : "l"(s))

// Scratch (static device globals; no allocation allowed)
__device__ float         g_alive[NB * HWSZ];       // unmasked new alive channel
__device__ unsigned char g_amask[NB * HWSZ];       // per-pixel alive map (post-mask)
__device__ unsigned char g_skip [NB * 256];        // per 16x4-region "phase A skipped"
__device__ unsigned      g_count;                  // barrier arrival counter
__device__ volatile unsigned g_sense;              // barrier sense

__device__ __forceinline__ float ldz(const float* __restrict__ ch, int y, int x) {
    if (y < 0 || y >= NH || x < 0 || x >= NW) return 0.0f;
    return __ldg(ch + y * NW + x);
}

// Grid barrier: all NBLK blocks are co-resident by construction.
__device__ __forceinline__ void grid_barrier(unsigned target) {
    __syncthreads();
    if (threadIdx.x == 0) {
        __threadfence();
        if (atomicAdd(&g_count, 1u) == NBLK - 1u) {
            g_count = 0u;
            __threadfence();
            g_sense = target;
        } else {
            while (g_sense != target) __nanosleep(64);
            __threadfence();
        }
    }
    __syncthreads();
}

// Dynamic smem layout (ull units)
#define S_W1  0
#define S_W2  (128*52)
#define S_B1  (S_W2 + 128*18)
#define S_B2  (S_B1 + 128)
#define SMEM_ULLS (S_B2 + 18)
#define SMEM_BYTES (SMEM_ULLS * 8)

__global__ __launch_bounds__(128, 2)
void nca_persistent(const float* __restrict__ init_state,
                    const float* __restrict__ rnd_all,
                    const float* __restrict__ W1, const float* __restrict__ b1,
                    const float* __restrict__ W2, const float* __restrict__ b2,
                    float* __restrict__ dev_path,   // [48,B,C,H,W]
                    float* __restrict__ final_out)  // [B,4,H,W]
{
    extern __shared__ ull smem[];
    const int tid = threadIdx.x;

    // ---- load duplicated weights once ----
    for (int i = tid; i < 128 * 52; i += 128) {
        int o = i / 52, c = i - o * 52;
        float w = (c < NPC) ? W1[o * NPC + c] : 0.0f;
        ull d; PK2(d, w, w); smem[S_W1 + i] = d;
    }
    for (int i = tid; i < 128 * 18; i += 128) {
        int o = i / 18, j = i - o * 18;
        float w = (j < NC) ? W2[j * NWID + o] : 0.0f;
        ull d; PK2(d, w, w); smem[S_W2 + i] = d;
    }
    { float w = b1[tid]; ull d; PK2(d, w, w); smem[S_B1 + tid] = d; }
    if (tid < 18) { float w = (tid < NC) ? b2[tid] : 0.0f; ull d; PK2(d, w, w); smem[S_B2 + tid] = d; }

    int bias_ok = (b1[tid] <= 0.0f);
    if (tid < NC) bias_ok = bias_ok && (b2[tid] == 0.0f);
    const int allz = __syncthreads_and(bias_ok);

    // ---- block geometry (fixed across all phases/steps) ----
    const int bid = blockIdx.x;          // 0..255
    const int b   = bid >> 6;            // batch
    const int tle = bid & 63;            // tile in 8x8 grid
    const int bx0 = (tle & 7) * 16;
    const int by0 = (tle >> 3) * 16;

    const int pr = tid & 7;              // pair index (x)
    const int lyr = tid >> 3;            // 0..15 row
    const int x0 = bx0 + pr * 2;
    const int y  = by0 + lyr;
    const int w  = tid >> 5;             // warp id 0..3
    const int ry = (by0 >> 2) + w;       // region row 0..31
    const int rx = bx0 >> 4;             // region col 0..7
    const int reg = b * 256 + ry * 8 + rx;
    const int pix = y * NW + x0;

    const ull* w1base = smem + S_W1;
    const ull* w2base = smem + S_W2;
    const ull* b1r    = smem + S_B1;

    unsigned bsense = 0;
    const float* cur = init_state;

    #pragma unroll 1
    for (int t = 0; t < NSTEP; t++) {
        float* dst = dev_path + (size_t)t * BCHW;
        float* dout = dst + b * CHW + pix;
        float* gal  = g_alive + b * HWSZ + pix;

        // ================= PHASE A: step compute =================
        bool skipped = false;
        if (t > 0 && allz) {
            // check 18x6 alive-map halo of this warp's 16x4 region
            const int hx0 = bx0 - 1, hy0 = ry * 4 - 1;
            unsigned v = 0;
            const int lane = tid & 31;
            #pragma unroll
            for (int i = lane; i < 108; i += 32) {
                int hx = hx0 + (i % 18);
                int hy = hy0 + (i / 18);
                if (hx >= 0 && hx < NW && hy >= 0 && hy < NH)
                    v |= __ldcg(&g_amask[b * HWSZ + hy * NW + hx]);
            }
            skipped = !__any_sync(0xFFFFFFFFu, v != 0);
        }

        if (skipped) {
            #pragma unroll
            for (int c = 0; c < NC; c++)
                *reinterpret_cast<ull*>(dout + c * HWSZ) = 0ULL;
            *reinterpret_cast<ull*>(gal) = 0ULL;
            if ((tid & 31) == 0) g_skip[reg] = 1;
        } else {
            if ((tid & 31) == 0) g_skip[reg] = 0;

            // ---- conv loads: 3x4 patch per channel ----
            ull p2[52];
            unsigned nz = 0u;
            const bool interior = (x0 >= 1) && (x0 + 2 < NW) && (y >= 1) && (y + 1 < NH);

            #pragma unroll
            for (int c = 0; c < NC; c++) {
                const float* ch = cur + (b * NC + c) * HWSZ + pix;
                float r0[4], r1[4], r2[4];
                if (interior) {
                    r0[0]=__ldg(ch-NW-1); r0[1]=__ldg(ch-NW); r0[2]=__ldg(ch-NW+1); r0[3]=__ldg(ch-NW+2);
                    r1[0]=__ldg(ch-1);    r1[1]=__ldg(ch);    r1[2]=__ldg(ch+1);    r1[3]=__ldg(ch+2);
                    r2[0]=__ldg(ch+NW-1); r2[1]=__ldg(ch+NW); r2[2]=__ldg(ch+NW+1); r2[3]=__ldg(ch+NW+2);
                } else {
                    const float* chb = cur + (b * NC + c) * HWSZ;
                    r0[0]=ldz(chb,y-1,x0-1); r0[1]=ldz(chb,y-1,x0); r0[2]=ldz(chb,y-1,x0+1); r0[3]=ldz(chb,y-1,x0+2);
                    r1[0]=ldz(chb,y  ,x0-1); r1[1]=ldz(chb,y  ,x0); r1[2]=ldz(chb,y  ,x0+1); r1[3]=ldz(chb,y  ,x0+2);
                    r2[0]=ldz(chb,y+1,x0-1); r2[1]=ldz(chb,y+1,x0); r2[2]=ldz(chb,y+1,x0+1); r2[3]=ldz(chb,y+1,x0+2);
                }
                nz |= __float_as_uint(r0[0]) | __float_as_uint(r0[1]) | __float_as_uint(r0[2]) | __float_as_uint(r0[3]);
                nz |= __float_as_uint(r1[0]) | __float_as_uint(r1[1]) | __float_as_uint(r1[2]) | __float_as_uint(r1[3]);
                nz |= __float_as_uint(r2[0]) | __float_as_uint(r2[1]) | __float_as_uint(r2[2]) | __float_as_uint(r2[3]);

                float gxA = ((r0[2]-r0[0]) + 2.0f*(r1[2]-r1[0]) + (r2[2]-r2[0])) * 0.125f;
                float gxB = ((r0[3]-r0[1]) + 2.0f*(r1[3]-r1[1]) + (r2[3]-r2[1])) * 0.125f;
                float gyA = ((r2[0]-r0[0]) + 2.0f*(r2[1]-r0[1]) + (r2[2]-r0[2])) * 0.125f;
                float gyB = ((r2[1]-r0[1]) + 2.0f*(r2[2]-r0[2]) + (r2[3]-r0[3])) * 0.125f;

                ull d;
                PK2(d, r1[1], r1[2]); p2[c]      = d;
                PK2(d, gxA,   gxB  ); p2[17 + c] = d;
                PK2(d, gyA,   gyB  ); p2[34 + c] = d;
            }
            p2[51] = 0ULL;

            const bool empty = allz && (nz == 0u);
            if (__all_sync(0xFFFFFFFFu, empty)) {
                #pragma unroll
                for (int c = 0; c < NC; c++)
                    *reinterpret_cast<ull*>(dout + c * HWSZ) = 0ULL;
                *reinterpret_cast<ull*>(gal) = 0ULL;
            } else {
                // rotation
                {
                    float angA, angB; UPK2(angA, angB, p2[16]);
                    float saA, caA, saB, caB;
                    sincosf(angA, &saA, &caA);
                    sincosf(angB, &saB, &caB);
                    ull ca2, sa2, nsa2;
                    PK2(ca2, caA, caB); PK2(sa2, saA, saB); PK2(nsa2, -saA, -saB);
                    #pragma unroll
                    for (int c = 0; c < NC; c++) {
                        ull gx2 = p2[17 + c], gy2 = p2[34 + c], u;
                        F2MUL2(u, ca2, gx2); F2FMA(u, sa2, gy2, u);  p2[17 + c] = u;
                        F2MUL2(u, ca2, gy2); F2FMA(u, nsa2, gx2, u); p2[34 + c] = u;
                    }
                }

                // MLP
                ull dx2[18];
                #pragma unroll
                for (int j = 0; j < 18; j++) dx2[j] = smem[S_B2 + j];

                const ull* w1r = w1base;
                const ull* w2r = w2base;
                #pragma unroll 2
                for (int o = 0; o < NWID; o++) {
                    ull acc0 = b1r[o];
                    ull acc1 = 0ULL;
                    const ulonglong2* r = reinterpret_cast<const ulonglong2*>(w1r);
                    #pragma unroll
                    for (int q = 0; q < 26; q++) {
                        ulonglong2 wv = r[q];
                        F2FMA(acc0, wv.x, p2[2*q],     acc0);
                        F2FMA(acc1, wv.y, p2[2*q + 1], acc1);
                    }
                    ull hs; F2ADD(hs, acc0, acc1);
                    float hA, hB; UPK2(hA, hB, hs);
                    hA = fmaxf(hA, 0.0f); hB = fmaxf(hB, 0.0f);
                    ull h2; PK2(h2, hA, hB);

                    const ulonglong2* r2 = reinterpret_cast<const ulonglong2*>(w2r);
                    #pragma unroll
                    for (int q = 0; q < 9; q++) {
                        ulonglong2 wv = r2[q];
                        F2FMA(dx2[2*q],     wv.x, h2, dx2[2*q]);
                        F2FMA(dx2[2*q + 1], wv.y, h2, dx2[2*q + 1]);
                    }
                    w1r += 52; w2r += 18;
                }

                // stochastic update
                const float2 rr = *reinterpret_cast<const float2*>(
                    rnd_all + ((size_t)t * NB + b) * HWSZ + pix);
                float mA = (rr.x < 0.5f) ? 1.0f : 0.0f;
                float mB = (rr.y < 0.5f) ? 1.0f : 0.0f;
                ull m2; PK2(m2, mA, mB);

                #pragma unroll
                for (int c = 0; c < NC; c++) {
                    ull nv; F2FMA(nv, dx2[c], m2, p2[c]);
                    *reinterpret_cast<ull*>(dout + c * HWSZ) = nv;
                    if (c == ALIVE_IDX) *reinterpret_cast<ull*>(gal) = nv;
                }
            }
        }

        bsense ^= 1u; grid_barrier(bsense);

        // ================= PHASE B: alive masking =================
        const bool last = (t == NSTEP - 1);
        const bool regskip = (g_skip[reg] != 0);   // same block wrote it

        if (!regskip) {
            // combined 3x4 maxpool patches for the pixel pair
            float mo[4] = {-1e30f,-1e30f,-1e30f,-1e30f};
            float mn[4] = {-1e30f,-1e30f,-1e30f,-1e30f};
            const float* oa = cur + (b * NC + ALIVE_IDX) * HWSZ;
            const unsigned naoff = b * HWSZ;
            #pragma unroll
            for (int dy = -1; dy <= 1; dy++) {
                int yy = y + dy;
                if (yy < 0 || yy >= NH) continue;
                #pragma unroll
                for (int dxx = -1; dxx <= 2; dxx++) {
                    int xx = x0 + dxx;
                    if (xx < 0 || xx >= NW) continue;
                    int idx = yy * NW + xx;
                    float ov = __ldg(oa + idx);
                    float nv = __ldcg(&g_alive[naoff + idx]);
                    mo[dxx + 1] = fmaxf(mo[dxx + 1], ov);
                    mn[dxx + 1] = fmaxf(mn[dxx + 1], nv);
                }
            }
            float moA = fmaxf(fmaxf(mo[0], mo[1]), mo[2]);
            float moB = fmaxf(fmaxf(mo[1], mo[2]), mo[3]);
            float mnA = fmaxf(fmaxf(mn[0], mn[1]), mn[2]);
            float mnB = fmaxf(fmaxf(mn[1], mn[2]), mn[3]);
            const bool aliveA = (moA > ALIVE_THR) && (mnA > ALIVE_THR);
            const bool aliveB = (moB > ALIVE_THR) && (mnB > ALIVE_THR);

            // zero dead pixels (alive pixels already hold correct values)
            if (!aliveA && !aliveB) {
                #pragma unroll
                for (int c = 0; c < NC; c++)
                    *reinterpret_cast<ull*>(dout + c * HWSZ) = 0ULL;
            } else if (!aliveA) {
                #pragma unroll
                for (int c = 0; c < NC; c++) dout[c * HWSZ] = 0.0f;
            } else if (!aliveB) {
                #pragma unroll
                for (int c = 0; c < NC; c++) dout[c * HWSZ + 1] = 0.0f;
            }
            uchar2 am; am.x = aliveA ? 1 : 0; am.y = aliveB ? 1 : 0;
            *reinterpret_cast<uchar2*>(&g_amask[b * HWSZ + pix]) = am;

            if (last) {
                #pragma unroll
                for (int c = 0; c < 4; c++) {
                    float vA = aliveA ? dout[c * HWSZ]     : 0.0f;
                    float vB = aliveB ? dout[c * HWSZ + 1] : 0.0f;
                    float2 fv; fv.x = vA; fv.y = vB;
                    *reinterpret_cast<float2*>(final_out + (b * 4 + c) * HWSZ + pix) = fv;
                }
            }
        } else if (last) {
            #pragma unroll
            for (int c = 0; c < 4; c++)
                *reinterpret_cast<ull*>(final_out + (b * 4 + c) * HWSZ + pix) = 0ULL;
        }

        bsense ^= 1u; grid_barrier(bsense);
        cur = dst;
    }
}

// ---------------------------------------------------------------------------
// Inputs: 0 init_state [4,17,128,128], 1 rand [48,4,1,128,128],
//         2 W1 [128,51], 3 b1 [128], 4 W2 [17,128], 5 b2 [17]
// Output f32: final[:, :4] (262144) then dev_path (48*4*17*128*128).
// ---------------------------------------------------------------------------
extern "C" void kernel_launch(void* const* d_in, const int* in_sizes, int n_in,
                              void* d_out, int out_size)
{
    const float* init_state = (const float*)d_in[0];
    const float* rnd        = (const float*)d_in[1];
    const float* W1         = (const float*)d_in[2];
    const float* b1         = (const float*)d_in[3];
    const float* W2         = (const float*)d_in[4];
    const float* b2         = (const float*)d_in[5];

    float* out      = (float*)d_out;
    float* final_p  = out;
    float* dev_path = out + FINAL_ELEMS;

    cudaFuncSetAttribute(nca_persistent,
                         cudaFuncAttributeMaxDynamicSharedMemorySize, SMEM_BYTES);

    nca_persistent<<<NBLK, 128, SMEM_BYTES>>>(init_state, rnd, W1, b1, W2, b2,
                                              dev_path, final_p);
}